// round 12
// baseline (speedup 1.0000x reference)
#include <cuda_runtime.h>
#include <cuda_fp16.h>
#include <math.h>
#include <stdint.h>

#define MAXN 400000
#define MAXB 10000
#define SH 136   // half-element row stride: 272B = 17 x 16B chunks -> conflict-free LDSM

// Scratch (static device globals; no allocations)
__device__ float g_ew[MAXN];
__device__ float g_anorm[MAXB];
__device__ float g_A[256];          // A0[0:128], A1[128:256]
__device__ float g_s[4];            // [0]=s0, [1]=s1
__device__ __half g_Wh[3][16384];   // fp16-rounded W1, W2, Wo

__device__ __forceinline__ float sspf(float x) {
    float ax = fabsf(x);
    float t = __expf(-ax);
    return fmaxf(x, 0.f) + __logf(1.f + t) - 0.69314718055994531f;
}

__device__ __forceinline__ uint32_t smem_u32(const void* p) {
    uint32_t a;
    asm("{ .reg .u64 t; cvta.to.shared.u64 t, %1; cvt.u32.u64 %0, t; }" : "=r"(a) : "l"(p));
    return a;
}

__device__ __forceinline__ void cpa16(uint32_t dst, const void* src) {
    asm volatile("cp.async.ca.shared.global [%0], [%1], 16;"
                 :: "r"(dst), "l"(__cvta_generic_to_global(src)) : "memory");
}
#define CP_COMMIT() asm volatile("cp.async.commit_group;" ::: "memory")
#define CP_WAIT0()  asm volatile("cp.async.wait_group 0;" ::: "memory")

__device__ __forceinline__ void ldsm4(uint32_t r[4], uint32_t addr) {
    asm volatile("ldmatrix.sync.aligned.m8n8.x4.shared.b16 {%0,%1,%2,%3}, [%4];"
                 : "=r"(r[0]), "=r"(r[1]), "=r"(r[2]), "=r"(r[3]) : "r"(addr));
}

__device__ __forceinline__ void mmaf16(float d[4], const uint32_t a[4], const uint32_t b[2]) {
    asm volatile(
        "mma.sync.aligned.m16n8k16.row.col.f32.f16.f16.f32 "
        "{%0,%1,%2,%3}, {%4,%5,%6,%7}, {%8,%9}, {%0,%1,%2,%3};"
        : "+f"(d[0]), "+f"(d[1]), "+f"(d[2]), "+f"(d[3])
        : "r"(a[0]), "r"(a[1]), "r"(a[2]), "r"(a[3]), "r"(b[0]), "r"(b[1]));
}

// 128x128x128 GEMM phase: warp computes 32x32 tile at (mb, nb).
// su (activations, half) and sw (weights, half) both [row][k], stride SH halves.
// A ldsm x4 -> {a0,a1,a2,a3}: rows(+0/+8) x k(+0/+8): row_off = lane&8, col_off = lane&16
// B ldsm x4 -> {b(nf)0, b(nf)1, b(nf+1)0, b(nf+1)1}: row_off = lane&16, col_off = lane&8
__device__ __forceinline__ void gemm32(uint32_t suB, uint32_t swB,
                                       int mb, int nb, int lane,
                                       float acc[2][4][4]) {
#pragma unroll
    for (int mf = 0; mf < 2; mf++)
#pragma unroll
        for (int nf = 0; nf < 4; nf++)
#pragma unroll
            for (int k = 0; k < 4; k++) acc[mf][nf][k] = 0.f;

    const int i = lane & 7;
    const uint32_t aadr = suB + 2u * (uint32_t)((mb + i + ((lane & 8) ? 8 : 0)) * SH
                                                + ((lane & 16) ? 8 : 0));
    const uint32_t badr = swB + 2u * (uint32_t)((nb + i + ((lane & 16) ? 8 : 0)) * SH
                                                + ((lane & 8) ? 8 : 0));
#pragma unroll
    for (int kb = 0; kb < 8; kb++) {
        uint32_t a0[4], a1[4], b0[4], b1[4];
        ldsm4(a0, aadr + kb * 32);
        ldsm4(a1, aadr + 16 * SH * 2 + kb * 32);
        ldsm4(b0, badr + kb * 32);
        ldsm4(b1, badr + 16 * SH * 2 + kb * 32);
        mmaf16(acc[0][0], a0, b0 + 0);
        mmaf16(acc[0][1], a0, b0 + 2);
        mmaf16(acc[0][2], a0, b1 + 0);
        mmaf16(acc[0][3], a0, b1 + 2);
        mmaf16(acc[1][0], a1, b0 + 0);
        mmaf16(acc[1][1], a1, b0 + 2);
        mmaf16(acc[1][2], a1, b1 + 0);
        mmaf16(acc[1][3], a1, b1 + 2);
    }
}

// load one 128x128 fp16 weight tile into padded smem via cp.async (2048 16B chunks)
__device__ __forceinline__ void issueW(uint32_t swB, const __half* __restrict__ src, int tid) {
#pragma unroll
    for (int it = 0; it < 4; it++) {
        int t = it * 512 + tid;
        int n = t >> 4, k8 = (t & 15) << 3;
        cpa16(swB + 2u * (uint32_t)(n * SH + k8), src + n * 128 + k8);
    }
    CP_COMMIT();
}

// ---------------------------------------------------------------------------
// Launch 1: fused prep (A0/A1/s0/s1) + fp16-round of W1/W2/Wo.
// ---------------------------------------------------------------------------
__global__ void k_prep_round(const float* __restrict__ Wq, const float* __restrict__ bq,
                             const float* __restrict__ Wk,
                             const float* __restrict__ W1, const float* __restrict__ W2,
                             const float* __restrict__ Wo) {
    if (blockIdx.x == 0) {
        int j = threadIdx.x;
        if (j < 128) {
            float a0 = 0.f, a1 = 0.f;
            for (int f = 0; f < 128; f++) {
                float wq = Wq[f * 128 + j];
                a0 += wq * Wk[2 * f];
                a1 += wq * Wk[2 * f + 1];
            }
            g_A[j] = a0;
            g_A[128 + j] = a1;
        }
        int wid = threadIdx.x >> 5, lane = threadIdx.x & 31;
        if (wid < 2) {
            float s = 0.f;
            for (int l = lane; l < 128; l += 32) s += bq[l] * Wk[2 * l + wid];
#pragma unroll
            for (int o = 16; o > 0; o >>= 1) s += __shfl_xor_sync(0xffffffffu, s, o);
            if (lane == 0) g_s[wid] = s;
        }
    } else {
        int t = (blockIdx.x - 1) * 1024 + threadIdx.x;
        if (t < 16384) g_Wh[0][t] = __float2half_rn(W1[t]);
        else if (t < 32768) g_Wh[1][t - 16384] = __float2half_rn(W2[t - 16384]);
        else g_Wh[2][t - 32768] = __float2half_rn(Wo[t - 32768]);
    }
}

// ---------------------------------------------------------------------------
// Launch 2: ew[i] = exp(w[i] - 10)  (softmax ratio is shift-invariant, so a
// fixed shift replaces the global max; no extra pass over N needed)
// ---------------------------------------------------------------------------
__global__ void k_w(const float* __restrict__ x, const float* __restrict__ ef,
                    const int* __restrict__ idx, int N) {
    __shared__ float A0s[128], A1s[128];
    int t = threadIdx.x;
    if (t < 128) A0s[t] = g_A[t];
    else A1s[t - 128] = g_A[t];
    __syncthreads();

    int warp = t >> 5, lane = t & 31;
    int i = blockIdx.x * 8 + warp;
    if (i >= N) return;
    int b = idx[i];
    float v = ef[b];
    float e0 = fmaxf(v, 0.f), e1 = fmaxf(-v, 0.f);
    float en0 = e0 / fmaxf(e0, 1.f), en1 = e1 / fmaxf(e1, 1.f);
    float4 xv = ((const float4*)(x + (size_t)i * 128))[lane];
    int j = lane * 4;
    float dot = xv.x * (en0 * A0s[j] + en1 * A1s[j]) +
                xv.y * (en0 * A0s[j + 1] + en1 * A1s[j + 1]) +
                xv.z * (en0 * A0s[j + 2] + en1 * A1s[j + 2]) +
                xv.w * (en0 * A0s[j + 3] + en1 * A1s[j + 3]);
#pragma unroll
    for (int o = 16; o > 0; o >>= 1) dot += __shfl_xor_sync(0xffffffffu, dot, o);
    if (lane == 0) {
        float wv = (dot + en0 * g_s[0] + en1 * g_s[1]) * 0.08838834764831845f;
        g_ew[i] = expf(wv - 10.f);
    }
}

// ---------------------------------------------------------------------------
// Launch 3: per-molecule segment sums (idx sorted; one warp per molecule)
// ---------------------------------------------------------------------------
__device__ __forceinline__ int lbound(const int* __restrict__ a, int n, int v) {
    int lo = 0, hi = n;
    while (lo < hi) {
        int m = (lo + hi) >> 1;
        if (a[m] < v) lo = m + 1;
        else hi = m;
    }
    return lo;
}

__global__ void k_seg(const int* __restrict__ idx, int N, int B) {
    int gw = (blockIdx.x * blockDim.x + threadIdx.x) >> 5;
    int lane = threadIdx.x & 31;
    if (gw >= B) return;
    int lo = lbound(idx, N, gw);
    int hi = lbound(idx, N, gw + 1);
    float s = 0.f;
    for (int i = lo + lane; i < hi; i += 32) s += g_ew[i];
#pragma unroll
    for (int o = 16; o > 0; o >>= 1) s += __shfl_xor_sync(0xffffffffu, s, o);
    if (lane == 0) g_anorm[gw] = s;
}

// ---------------------------------------------------------------------------
// Launch 4: persistent fused MLP, fp16 mma + ldmatrix, 128-row tiles,
// 2 CTAs/SM (regs capped at 64 via launch bounds).
// smem bytes: su[128*SH*2]=34816 | wbuf[128*SH*2]=34816 | sp,sq[128f each] |
//             swx,swy[128f each] | sred[16f]  => 71744 B/CTA
// ---------------------------------------------------------------------------
__global__ void __launch_bounds__(512, 2)
k_mlp_mma(const float* __restrict__ ef, const int* __restrict__ idx,
          const float* __restrict__ Wv, float* __restrict__ out,
          int N, int B, int niter) {
    extern __shared__ char smem[];
    __half* su = (__half*)smem;                    // 128 x SH halves
    __half* wb = (__half*)(smem + 34816);          // 128 x SH halves
    float* sp = (float*)(smem + 69632);
    float* sq = sp + 128;
    float* swx = sq + 128;
    float* swy = swx + 128;
    float* sred = swy + 128;

    const uint32_t suB = smem_u32(smem);
    const uint32_t wbB = suB + 34816u;

    const int tid = threadIdx.x;
    const int lane = tid & 31, wid = tid >> 5;
    const int mb = (wid >> 2) * 32, nb = (wid & 3) * 32;
    const int lq = lane >> 2, lr = lane & 3;

    if (tid < 128) {
        float2 wv = ((const float2*)Wv)[tid];
        swx[tid] = wv.x;
        swy[tid] = wv.y;
    }

    // deterministic per-CTA sum S = sum(anorm)
    {
        float s = 0.f;
        for (int i = tid; i < B; i += 512) s += g_anorm[i];
#pragma unroll
        for (int o = 16; o > 0; o >>= 1) s += __shfl_xor_sync(0xffffffffu, s, o);
        if (lane == 0) sred[wid] = s;
    }
    __syncthreads();
    float Sg = 0.f;
#pragma unroll
    for (int k = 0; k < 16; k++) Sg += sred[k];
    const float epsS = 1e-8f * Sg;

    issueW(wbB, g_Wh[0], tid);  // prologue: W1

    float acc[2][4][4];

    for (int iter = blockIdx.x; iter < niter; iter += gridDim.x) {
        const int row0 = iter * 128;

        if (tid < 128) {
            int i = row0 + tid;
            float pc = 0.f, qc = 0.f;
            if (i < N) {
                int b = idx[i];
                float v = ef[b];
                float c = g_ew[i] / (g_anorm[b] + epsS);
                pc = c * fmaxf(v, 0.f);
                qc = c * fmaxf(-v, 0.f);
            }
            sp[tid] = pc;
            sq[tid] = qc;
        }
        __syncthreads();

        // stage 0: u = fp16(ssp(x)), x = p[r]*wx[c] + q[r]*wy[c]; 8 halves/thread/it
#pragma unroll
        for (int it = 0; it < 4; it++) {
            int f = it * 512 + tid;
            int r = f >> 4, c8 = (f & 15) << 3;
            float pr = sp[r], qr = sq[r];
            __half2 h[4];
#pragma unroll
            for (int j = 0; j < 4; j++) {
                float v0 = sspf(pr * swx[c8 + 2 * j] + qr * swy[c8 + 2 * j]);
                float v1 = sspf(pr * swx[c8 + 2 * j + 1] + qr * swy[c8 + 2 * j + 1]);
                h[j] = __floats2half2_rn(v0, v1);
            }
            *(uint4*)(su + r * SH + c8) = *(uint4*)h;
        }
        CP_WAIT0();  // W1 ready
        __syncthreads();

        // GEMM1: D = u @ W1^T
        gemm32(suB, wbB, mb, nb, lane, acc);
        __syncthreads();

        issueW(wbB, g_Wh[1], tid);  // W2 (overlaps epi1)

        // epi1: u = fp16(ssp(D))
#pragma unroll
        for (int mf = 0; mf < 2; mf++) {
            int r = mb + mf * 16 + lq;
#pragma unroll
            for (int nf = 0; nf < 4; nf++) {
                int c = nb + nf * 8 + 2 * lr;
                *(__half2*)(su + r * SH + c) =
                    __floats2half2_rn(sspf(acc[mf][nf][0]), sspf(acc[mf][nf][1]));
                *(__half2*)(su + (r + 8) * SH + c) =
                    __floats2half2_rn(sspf(acc[mf][nf][2]), sspf(acc[mf][nf][3]));
            }
        }
        CP_WAIT0();  // W2 ready
        __syncthreads();

        // GEMM2: D = u @ W2^T
        gemm32(suB, wbB, mb, nb, lane, acc);
        __syncthreads();

        issueW(wbB, g_Wh[2], tid);  // Wo (overlaps epi2)

        // epi2: u = fp16(ssp(x + D)), x regenerated
#pragma unroll
        for (int mf = 0; mf < 2; mf++) {
            int r = mb + mf * 16 + lq;
            float p0 = sp[r], q0 = sq[r];
            float p1 = sp[r + 8], q1 = sq[r + 8];
#pragma unroll
            for (int nf = 0; nf < 4; nf++) {
                int c = nb + nf * 8 + 2 * lr;
                float wxa = swx[c], wxb = swx[c + 1];
                float wya = swy[c], wyb = swy[c + 1];
                *(__half2*)(su + r * SH + c) = __floats2half2_rn(
                    sspf(p0 * wxa + q0 * wya + acc[mf][nf][0]),
                    sspf(p0 * wxb + q0 * wyb + acc[mf][nf][1]));
                *(__half2*)(su + (r + 8) * SH + c) = __floats2half2_rn(
                    sspf(p1 * wxa + q1 * wya + acc[mf][nf][2]),
                    sspf(p1 * wxb + q1 * wyb + acc[mf][nf][3]));
            }
        }
        CP_WAIT0();  // Wo ready
        __syncthreads();

        // GEMM3: D = u @ Wo^T
        gemm32(suB, wbB, mb, nb, lane, acc);
        __syncthreads();

        issueW(wbB, g_Wh[0], tid);  // next iteration's W1

        // direct global stores
#pragma unroll
        for (int mf = 0; mf < 2; mf++) {
            int r = row0 + mb + mf * 16 + lq;
#pragma unroll
            for (int nf = 0; nf < 4; nf++) {
                int c = nb + nf * 8 + 2 * lr;
                if (r < N)
                    *(float2*)(out + (size_t)r * 128 + c) =
                        make_float2(acc[mf][nf][0], acc[mf][nf][1]);
                if (r + 8 < N)
                    *(float2*)(out + (size_t)(r + 8) * 128 + c) =
                        make_float2(acc[mf][nf][2], acc[mf][nf][3]);
            }
        }
        __syncthreads();  // su/sp safe to overwrite next iteration
    }
}

// ---------------------------------------------------------------------------
extern "C" void kernel_launch(void* const* d_in, const int* in_sizes, int n_in,
                              void* d_out, int out_size) {
    const float* x   = (const float*)d_in[0];
    const float* ef  = (const float*)d_in[1];
    const int*   idx = (const int*)d_in[2];
    const float* Wq  = (const float*)d_in[3];
    const float* bq  = (const float*)d_in[4];
    const float* Wk  = (const float*)d_in[5];
    const float* Wv  = (const float*)d_in[6];
    const float* W1  = (const float*)d_in[7];
    const float* W2  = (const float*)d_in[8];
    const float* Wo  = (const float*)d_in[9];
    float* out = (float*)d_out;

    int B = in_sizes[1];
    int N = in_sizes[2];

    k_prep_round<<<49, 1024>>>(Wq, bq, Wk, W1, W2, Wo);

    k_w<<<(N + 7) / 8, 256>>>(x, ef, idx, N);
    k_seg<<<(B + 7) / 8, 256>>>(idx, N, B);

    int niter = (N + 127) / 128;
    int grid = niter < 296 ? niter : 296;
    cudaFuncSetAttribute(k_mlp_mma, cudaFuncAttributeMaxDynamicSharedMemorySize, 71744);
    k_mlp_mma<<<grid, 512, 71744>>>(ef, idx, Wv, out, N, B, niter);
}

// round 13
// speedup vs baseline: 1.0129x; 1.0129x over previous
#include <cuda_runtime.h>
#include <cuda_fp16.h>
#include <math.h>
#include <stdint.h>

#define MAXN 400000
#define MAXB 10000
#define SH 136   // half-element row stride: 272B = 17 x 16B chunks -> conflict-free LDSM

// Scratch (static device globals; no allocations)
__device__ float g_ew[MAXN];
__device__ float g_anorm[MAXB];
__device__ float g_A[256];          // A0[0:128], A1[128:256]
__device__ float g_s[4];            // [0]=s0, [1]=s1
__device__ __half g_Wh[3][16384];   // fp16-rounded W1, W2, Wo

__device__ __forceinline__ float sspf(float x) {
    float ax = fabsf(x);
    float t = __expf(-ax);
    return fmaxf(x, 0.f) + __logf(1.f + t) - 0.69314718055994531f;
}

__device__ __forceinline__ uint32_t smem_u32(const void* p) {
    uint32_t a;
    asm("{ .reg .u64 t; cvta.to.shared.u64 t, %1; cvt.u32.u64 %0, t; }" : "=r"(a) : "l"(p));
    return a;
}

__device__ __forceinline__ void cpa16(uint32_t dst, const void* src) {
    asm volatile("cp.async.ca.shared.global [%0], [%1], 16;"
                 :: "r"(dst), "l"(__cvta_generic_to_global(src)) : "memory");
}
#define CP_COMMIT() asm volatile("cp.async.commit_group;" ::: "memory")
#define CP_WAIT0()  asm volatile("cp.async.wait_group 0;" ::: "memory")

__device__ __forceinline__ void ldsm4(uint32_t r[4], uint32_t addr) {
    asm volatile("ldmatrix.sync.aligned.m8n8.x4.shared.b16 {%0,%1,%2,%3}, [%4];"
                 : "=r"(r[0]), "=r"(r[1]), "=r"(r[2]), "=r"(r[3]) : "r"(addr));
}

__device__ __forceinline__ void mmaf16(float d[4], const uint32_t a[4], const uint32_t b[2]) {
    asm volatile(
        "mma.sync.aligned.m16n8k16.row.col.f32.f16.f16.f32 "
        "{%0,%1,%2,%3}, {%4,%5,%6,%7}, {%8,%9}, {%0,%1,%2,%3};"
        : "+f"(d[0]), "+f"(d[1]), "+f"(d[2]), "+f"(d[3])
        : "r"(a[0]), "r"(a[1]), "r"(a[2]), "r"(a[3]), "r"(b[0]), "r"(b[1]));
}

// 128x128x128 GEMM phase: warp computes 32x32 tile at (mb, nb).
// su (activations, half) and sw (weights, half) both [row][k], stride SH halves.
// A ldsm x4 -> {a0,a1,a2,a3}: rows(+0/+8) x k(+0/+8): row_off = lane&8, col_off = lane&16
// B ldsm x4 -> {b(nf)0, b(nf)1, b(nf+1)0, b(nf+1)1}: row_off = lane&16, col_off = lane&8
__device__ __forceinline__ void gemm32(uint32_t suB, uint32_t swB,
                                       int mb, int nb, int lane,
                                       float acc[2][4][4]) {
#pragma unroll
    for (int mf = 0; mf < 2; mf++)
#pragma unroll
        for (int nf = 0; nf < 4; nf++)
#pragma unroll
            for (int k = 0; k < 4; k++) acc[mf][nf][k] = 0.f;

    const int i = lane & 7;
    const uint32_t aadr = suB + 2u * (uint32_t)((mb + i + ((lane & 8) ? 8 : 0)) * SH
                                                + ((lane & 16) ? 8 : 0));
    const uint32_t badr = swB + 2u * (uint32_t)((nb + i + ((lane & 16) ? 8 : 0)) * SH
                                                + ((lane & 8) ? 8 : 0));
#pragma unroll
    for (int kb = 0; kb < 8; kb++) {
        uint32_t a0[4], a1[4], b0[4], b1[4];
        ldsm4(a0, aadr + kb * 32);
        ldsm4(a1, aadr + 16 * SH * 2 + kb * 32);
        ldsm4(b0, badr + kb * 32);
        ldsm4(b1, badr + 16 * SH * 2 + kb * 32);
        mmaf16(acc[0][0], a0, b0 + 0);
        mmaf16(acc[0][1], a0, b0 + 2);
        mmaf16(acc[0][2], a0, b1 + 0);
        mmaf16(acc[0][3], a0, b1 + 2);
        mmaf16(acc[1][0], a1, b0 + 0);
        mmaf16(acc[1][1], a1, b0 + 2);
        mmaf16(acc[1][2], a1, b1 + 0);
        mmaf16(acc[1][3], a1, b1 + 2);
    }
}

// load one 128x128 fp16 weight tile into padded smem via cp.async (2048 16B chunks)
__device__ __forceinline__ void issueW(uint32_t swB, const __half* __restrict__ src, int tid) {
#pragma unroll
    for (int it = 0; it < 4; it++) {
        int t = it * 512 + tid;
        int n = t >> 4, k8 = (t & 15) << 3;
        cpa16(swB + 2u * (uint32_t)(n * SH + k8), src + n * 128 + k8);
    }
    CP_COMMIT();
}

// ---------------------------------------------------------------------------
// Launch 1: fused prep (A0/A1/s0/s1) + fp16-round of W1/W2/Wo.
// ---------------------------------------------------------------------------
__global__ void k_prep_round(const float* __restrict__ Wq, const float* __restrict__ bq,
                             const float* __restrict__ Wk,
                             const float* __restrict__ W1, const float* __restrict__ W2,
                             const float* __restrict__ Wo) {
    if (blockIdx.x == 0) {
        int j = threadIdx.x;
        if (j < 128) {
            float a0 = 0.f, a1 = 0.f;
            for (int f = 0; f < 128; f++) {
                float wq = Wq[f * 128 + j];
                a0 += wq * Wk[2 * f];
                a1 += wq * Wk[2 * f + 1];
            }
            g_A[j] = a0;
            g_A[128 + j] = a1;
        }
        int wid = threadIdx.x >> 5, lane = threadIdx.x & 31;
        if (wid < 2) {
            float s = 0.f;
            for (int l = lane; l < 128; l += 32) s += bq[l] * Wk[2 * l + wid];
#pragma unroll
            for (int o = 16; o > 0; o >>= 1) s += __shfl_xor_sync(0xffffffffu, s, o);
            if (lane == 0) g_s[wid] = s;
        }
    } else {
        int t = (blockIdx.x - 1) * 1024 + threadIdx.x;
        if (t < 16384) g_Wh[0][t] = __float2half_rn(W1[t]);
        else if (t < 32768) g_Wh[1][t - 16384] = __float2half_rn(W2[t - 16384]);
        else g_Wh[2][t - 32768] = __float2half_rn(Wo[t - 32768]);
    }
}

// ---------------------------------------------------------------------------
// Launch 2: ew[i] = exp(w[i] - 10)  (softmax ratio is shift-invariant, so a
// fixed shift replaces the global max; no extra pass over N needed)
// ---------------------------------------------------------------------------
__global__ void k_w(const float* __restrict__ x, const float* __restrict__ ef,
                    const int* __restrict__ idx, int N) {
    __shared__ float A0s[128], A1s[128];
    int t = threadIdx.x;
    if (t < 128) A0s[t] = g_A[t];
    else A1s[t - 128] = g_A[t];
    __syncthreads();

    int warp = t >> 5, lane = t & 31;
    int i = blockIdx.x * 8 + warp;
    if (i >= N) return;
    int b = idx[i];
    float v = ef[b];
    float e0 = fmaxf(v, 0.f), e1 = fmaxf(-v, 0.f);
    float en0 = e0 / fmaxf(e0, 1.f), en1 = e1 / fmaxf(e1, 1.f);
    float4 xv = ((const float4*)(x + (size_t)i * 128))[lane];
    int j = lane * 4;
    float dot = xv.x * (en0 * A0s[j] + en1 * A1s[j]) +
                xv.y * (en0 * A0s[j + 1] + en1 * A1s[j + 1]) +
                xv.z * (en0 * A0s[j + 2] + en1 * A1s[j + 2]) +
                xv.w * (en0 * A0s[j + 3] + en1 * A1s[j + 3]);
#pragma unroll
    for (int o = 16; o > 0; o >>= 1) dot += __shfl_xor_sync(0xffffffffu, dot, o);
    if (lane == 0) {
        float wv = (dot + en0 * g_s[0] + en1 * g_s[1]) * 0.08838834764831845f;
        g_ew[i] = expf(wv - 10.f);
    }
}

// ---------------------------------------------------------------------------
// Launch 3: per-molecule segment sums (idx sorted; one warp per molecule)
// ---------------------------------------------------------------------------
__device__ __forceinline__ int lbound(const int* __restrict__ a, int n, int v) {
    int lo = 0, hi = n;
    while (lo < hi) {
        int m = (lo + hi) >> 1;
        if (a[m] < v) lo = m + 1;
        else hi = m;
    }
    return lo;
}

__global__ void k_seg(const int* __restrict__ idx, int N, int B) {
    int gw = (blockIdx.x * blockDim.x + threadIdx.x) >> 5;
    int lane = threadIdx.x & 31;
    if (gw >= B) return;
    int lo = lbound(idx, N, gw);
    int hi = lbound(idx, N, gw + 1);
    float s = 0.f;
    for (int i = lo + lane; i < hi; i += 32) s += g_ew[i];
#pragma unroll
    for (int o = 16; o > 0; o >>= 1) s += __shfl_xor_sync(0xffffffffu, s, o);
    if (lane == 0) g_anorm[gw] = s;
}

// ---------------------------------------------------------------------------
// Launch 4: persistent fused MLP, fp16 mma + ldmatrix, 128-row tiles,
// 2 CTAs/SM (regs capped at 64 via launch bounds).
// smem bytes: su[128*SH*2]=34816 | wbuf[128*SH*2]=34816 | sp,sq[128f each] |
//             swx,swy[128f each] | sred[16f]  => 71744 B/CTA
// ---------------------------------------------------------------------------
__global__ void __launch_bounds__(512, 2)
k_mlp_mma(const float* __restrict__ ef, const int* __restrict__ idx,
          const float* __restrict__ Wv, float* __restrict__ out,
          int N, int B, int niter) {
    extern __shared__ char smem[];
    __half* su = (__half*)smem;                    // 128 x SH halves
    __half* wb = (__half*)(smem + 34816);          // 128 x SH halves
    float* sp = (float*)(smem + 69632);
    float* sq = sp + 128;
    float* swx = sq + 128;
    float* swy = swx + 128;
    float* sred = swy + 128;

    const uint32_t suB = smem_u32(smem);
    const uint32_t wbB = suB + 34816u;

    const int tid = threadIdx.x;
    const int lane = tid & 31, wid = tid >> 5;
    const int mb = (wid >> 2) * 32, nb = (wid & 3) * 32;
    const int lq = lane >> 2, lr = lane & 3;

    if (tid < 128) {
        float2 wv = ((const float2*)Wv)[tid];
        swx[tid] = wv.x;
        swy[tid] = wv.y;
    }

    // deterministic per-CTA sum S = sum(anorm)
    {
        float s = 0.f;
        for (int i = tid; i < B; i += 512) s += g_anorm[i];
#pragma unroll
        for (int o = 16; o > 0; o >>= 1) s += __shfl_xor_sync(0xffffffffu, s, o);
        if (lane == 0) sred[wid] = s;
    }
    __syncthreads();
    float Sg = 0.f;
#pragma unroll
    for (int k = 0; k < 16; k++) Sg += sred[k];
    const float epsS = 1e-8f * Sg;

    issueW(wbB, g_Wh[0], tid);  // prologue: W1

    float acc[2][4][4];

    for (int iter = blockIdx.x; iter < niter; iter += gridDim.x) {
        const int row0 = iter * 128;

        if (tid < 128) {
            int i = row0 + tid;
            float pc = 0.f, qc = 0.f;
            if (i < N) {
                int b = idx[i];
                float v = ef[b];
                float c = g_ew[i] / (g_anorm[b] + epsS);
                pc = c * fmaxf(v, 0.f);
                qc = c * fmaxf(-v, 0.f);
            }
            sp[tid] = pc;
            sq[tid] = qc;
        }
        __syncthreads();

        // stage 0: u = fp16(ssp(x)), x = p[r]*wx[c] + q[r]*wy[c]; 8 halves/thread/it
#pragma unroll
        for (int it = 0; it < 4; it++) {
            int f = it * 512 + tid;
            int r = f >> 4, c8 = (f & 15) << 3;
            float pr = sp[r], qr = sq[r];
            __half2 h[4];
#pragma unroll
            for (int j = 0; j < 4; j++) {
                float v0 = sspf(pr * swx[c8 + 2 * j] + qr * swy[c8 + 2 * j]);
                float v1 = sspf(pr * swx[c8 + 2 * j + 1] + qr * swy[c8 + 2 * j + 1]);
                h[j] = __floats2half2_rn(v0, v1);
            }
            *(uint4*)(su + r * SH + c8) = *(uint4*)h;
        }
        CP_WAIT0();  // W1 ready
        __syncthreads();

        // GEMM1: D = u @ W1^T
        gemm32(suB, wbB, mb, nb, lane, acc);
        __syncthreads();

        issueW(wbB, g_Wh[1], tid);  // W2 (overlaps epi1)

        // epi1: u = fp16(ssp(D))
#pragma unroll
        for (int mf = 0; mf < 2; mf++) {
            int r = mb + mf * 16 + lq;
#pragma unroll
            for (int nf = 0; nf < 4; nf++) {
                int c = nb + nf * 8 + 2 * lr;
                *(__half2*)(su + r * SH + c) =
                    __floats2half2_rn(sspf(acc[mf][nf][0]), sspf(acc[mf][nf][1]));
                *(__half2*)(su + (r + 8) * SH + c) =
                    __floats2half2_rn(sspf(acc[mf][nf][2]), sspf(acc[mf][nf][3]));
            }
        }
        CP_WAIT0();  // W2 ready
        __syncthreads();

        // GEMM2: D = u @ W2^T
        gemm32(suB, wbB, mb, nb, lane, acc);
        __syncthreads();

        issueW(wbB, g_Wh[2], tid);  // Wo (overlaps epi2)

        // epi2: u = fp16(ssp(x + D)), x regenerated
#pragma unroll
        for (int mf = 0; mf < 2; mf++) {
            int r = mb + mf * 16 + lq;
            float p0 = sp[r], q0 = sq[r];
            float p1 = sp[r + 8], q1 = sq[r + 8];
#pragma unroll
            for (int nf = 0; nf < 4; nf++) {
                int c = nb + nf * 8 + 2 * lr;
                float wxa = swx[c], wxb = swx[c + 1];
                float wya = swy[c], wyb = swy[c + 1];
                *(__half2*)(su + r * SH + c) = __floats2half2_rn(
                    sspf(p0 * wxa + q0 * wya + acc[mf][nf][0]),
                    sspf(p0 * wxb + q0 * wyb + acc[mf][nf][1]));
                *(__half2*)(su + (r + 8) * SH + c) = __floats2half2_rn(
                    sspf(p1 * wxa + q1 * wya + acc[mf][nf][2]),
                    sspf(p1 * wxb + q1 * wyb + acc[mf][nf][3]));
            }
        }
        CP_WAIT0();  // Wo ready
        __syncthreads();

        // GEMM3: D = u @ Wo^T
        gemm32(suB, wbB, mb, nb, lane, acc);
        __syncthreads();

        issueW(wbB, g_Wh[0], tid);  // next iteration's W1

        // direct global stores
#pragma unroll
        for (int mf = 0; mf < 2; mf++) {
            int r = row0 + mb + mf * 16 + lq;
#pragma unroll
            for (int nf = 0; nf < 4; nf++) {
                int c = nb + nf * 8 + 2 * lr;
                if (r < N)
                    *(float2*)(out + (size_t)r * 128 + c) =
                        make_float2(acc[mf][nf][0], acc[mf][nf][1]);
                if (r + 8 < N)
                    *(float2*)(out + (size_t)(r + 8) * 128 + c) =
                        make_float2(acc[mf][nf][2], acc[mf][nf][3]);
            }
        }
        __syncthreads();  // su/sp safe to overwrite next iteration
    }
}

// ---------------------------------------------------------------------------
extern "C" void kernel_launch(void* const* d_in, const int* in_sizes, int n_in,
                              void* d_out, int out_size) {
    const float* x   = (const float*)d_in[0];
    const float* ef  = (const float*)d_in[1];
    const int*   idx = (const int*)d_in[2];
    const float* Wq  = (const float*)d_in[3];
    const float* bq  = (const float*)d_in[4];
    const float* Wk  = (const float*)d_in[5];
    const float* Wv  = (const float*)d_in[6];
    const float* W1  = (const float*)d_in[7];
    const float* W2  = (const float*)d_in[8];
    const float* Wo  = (const float*)d_in[9];
    float* out = (float*)d_out;

    int B = in_sizes[1];
    int N = in_sizes[2];

    k_prep_round<<<49, 1024>>>(Wq, bq, Wk, W1, W2, Wo);

    k_w<<<(N + 7) / 8, 256>>>(x, ef, idx, N);
    k_seg<<<(B + 7) / 8, 256>>>(idx, N, B);

    int niter = (N + 127) / 128;
    int grid = niter < 296 ? niter : 296;
    cudaFuncSetAttribute(k_mlp_mma, cudaFuncAttributeMaxDynamicSharedMemorySize, 71744);
    k_mlp_mma<<<grid, 512, 71744>>>(ef, idx, Wv, out, N, B, niter);
}